// round 11
// baseline (speedup 1.0000x reference)
#include <cuda_runtime.h>

// DifferentiableNERF, round 11.
// ILP2: each 128-thread block processes TWO chains; every per-chain value is
// an array [2] with the chain loop innermost (unrolled), so the two
// independent placeF dependency chains interleave at instruction level.
// Effective latency hiding = warps x 2 (R8 showed longer SERIAL chains lose;
// this widens the chain in PARALLEL instead).
// Otherwise R6/R9 structure: SEG=4, transposed conflict-free SMEM per chain,
// closed-form frame propagation + end-of-segment Gram-Schmidt, matrix
// Kogge-Stone scan, division-free incremental writeout.

namespace {

constexpr int L_CONST = 512;
constexpr int NSTEP = L_CONST - 1;   // 511
constexpr int SEG = 4;               // steps per thread per chain
constexpr int THREADS = 128;
constexpr int NC = 2;                // chains per block
constexpr int CHAIN_FLOATS = 3 * L_CONST * 3;  // 4608
constexpr int ROWS = SEG * 9;        // 36
constexpr int COLS = THREADS + 1;    // 129 (conflict-free stride)

struct V3 { float x, y, z; };

__device__ __forceinline__ V3 vsub(V3 a, V3 b) { return {a.x - b.x, a.y - b.y, a.z - b.z}; }
__device__ __forceinline__ V3 vcross(V3 a, V3 b) {
    return { a.y * b.z - a.z * b.y,
             a.z * b.x - a.x * b.z,
             a.x * b.y - a.y * b.x };
}
__device__ __forceinline__ float vdot(V3 a, V3 b) { return a.x * b.x + a.y * b.y + a.z * b.z; }
__device__ __forceinline__ V3 vunit(V3 a) {
    float r = rsqrtf(fmaxf(vdot(a, a), 1e-30f));
    return { a.x * r, a.y * r, a.z * r };
}

struct Aff { float m[9]; float t[3]; };

__device__ __forceinline__ Aff identityAff() {
    Aff r;
    r.m[0] = 1.f; r.m[1] = 0.f; r.m[2] = 0.f;
    r.m[3] = 0.f; r.m[4] = 1.f; r.m[5] = 0.f;
    r.m[6] = 0.f; r.m[7] = 0.f; r.m[8] = 1.f;
    r.t[0] = 0.f; r.t[1] = 0.f; r.t[2] = 0.f;
    return r;
}

// (A o B)(x) = A(B(x))
__device__ __forceinline__ Aff compose(const Aff& A, const Aff& B) {
    Aff r;
#pragma unroll
    for (int i = 0; i < 3; i++) {
#pragma unroll
        for (int j = 0; j < 3; j++) {
            r.m[3 * i + j] = A.m[3 * i + 0] * B.m[0 + j]
                           + A.m[3 * i + 1] * B.m[3 + j]
                           + A.m[3 * i + 2] * B.m[6 + j];
        }
        r.t[i] = A.m[3 * i + 0] * B.t[0]
               + A.m[3 * i + 1] * B.t[1]
               + A.m[3 * i + 2] * B.t[2] + A.t[i];
    }
    return r;
}

__device__ __forceinline__ Aff invRigid(const Aff& A) {
    Aff r;
    r.m[0] = A.m[0]; r.m[1] = A.m[3]; r.m[2] = A.m[6];
    r.m[3] = A.m[1]; r.m[4] = A.m[4]; r.m[5] = A.m[7];
    r.m[6] = A.m[2]; r.m[7] = A.m[5]; r.m[8] = A.m[8];
#pragma unroll
    for (int i = 0; i < 3; i++) {
        r.t[i] = -(r.m[3 * i + 0] * A.t[0] + r.m[3 * i + 1] * A.t[1] + r.m[3 * i + 2] * A.t[2]);
    }
    return r;
}

// Orthonormal placement frame: ex = bond dir, ez = plane normal, ey = ez x ex.
struct Frame { V3 ex, ey, ez; V3 c; };

__device__ __forceinline__ V3 placeF(Frame& F, float ang, float len, float tor) {
    float st, ct, sa, ca;
    __sincosf(tor, &st, &ct);
    __sincosf(ang, &sa, &ca);
    float k2 = ct * sa, k3 = st * sa;
    V3 u  = { k3 * F.ez.x + (k2 * F.ey.x - ca * F.ex.x),
              k3 * F.ez.y + (k2 * F.ey.y - ca * F.ex.y),
              k3 * F.ez.z + (k2 * F.ey.z - ca * F.ex.z) };
    V3 p  = { F.c.x + len * u.x, F.c.y + len * u.y, F.c.z + len * u.z };
    V3 ez2 = { ct * F.ez.x - st * F.ey.x,
               ct * F.ez.y - st * F.ey.y,
               ct * F.ez.z - st * F.ey.z };
    V3 ey2 = vcross(ez2, u);
    F.ex = u; F.ey = ey2; F.ez = ez2; F.c = p;
    return p;
}

__device__ __forceinline__ Frame frameOfTriplet(V3 a, V3 b, V3 c) {
    Frame F;
    F.ex = vunit(vsub(c, b));
    F.ez = vunit(vcross(vsub(b, a), F.ex));
    F.ey = vcross(F.ez, F.ex);
    F.c = c;
    return F;
}

// Gram-Schmidt: restore exact orthonormality of the propagated frame.
__device__ __forceinline__ void orthonormalize(Frame& F) {
    V3 ex = vunit(F.ex);
    float d = vdot(F.ez, ex);
    V3 ez = { F.ez.x - d * ex.x, F.ez.y - d * ex.y, F.ez.z - d * ex.z };
    ez = vunit(ez);
    F.ex = ex;
    F.ez = ez;
    F.ey = vcross(ez, ex);
}

__device__ __forceinline__ Aff frameToAff(const Frame& F) {
    Aff A;
    A.m[0] = F.ex.x; A.m[1] = F.ey.x; A.m[2] = F.ez.x;
    A.m[3] = F.ex.y; A.m[4] = F.ey.y; A.m[5] = F.ez.y;
    A.m[6] = F.ex.z; A.m[7] = F.ey.z; A.m[8] = F.ez.z;
    A.t[0] = F.c.x;  A.t[1] = F.c.y;  A.t[2] = F.c.z;
    return A;
}

__device__ __forceinline__ Aff shflUpAff(const Aff& A, int delta) {
    Aff r;
#pragma unroll
    for (int k = 0; k < 9; k++) r.m[k] = __shfl_up_sync(0xffffffffu, A.m[k], delta);
#pragma unroll
    for (int k = 0; k < 3; k++) r.t[k] = __shfl_up_sync(0xffffffffu, A.t[k], delta);
    return r;
}

__constant__ float c9[9] = {
    17.047f, 14.099f, 3.625f,
    16.967f, 12.784f, 4.338f,
    15.685f, 12.755f, 5.133f
};

__global__ __launch_bounds__(THREADS, 4)
void nerf_kernel(const float* __restrict__ phi,
                 const float* __restrict__ psi,
                 const float* __restrict__ omega,
                 const float* __restrict__ bl,
                 const float* __restrict__ ba,
                 float* __restrict__ out) {
    __shared__ float traj[NC][ROWS][COLS];
    __shared__ float warpTot[NC][3][12];   // inclusive totals of warps 0..2

    const int tid  = threadIdx.x;
    const int lane = tid & 31;
    const int warp = tid >> 5;
    const int chain0 = blockIdx.x * NC;

    const int base = tid * SEG;

    const V3 A0 = {17.047f, 14.099f, 3.625f};
    const V3 B0 = {16.967f, 12.784f, 4.338f};
    const V3 C0 = {15.685f, 12.755f, 5.133f};

    const float* phiR[NC];
    const float* psiS[NC];
    const float* omgS[NC];
    const float* blS[NC];
    const float* baS[NC];
#pragma unroll
    for (int c = 0; c < NC; c++) {
        int ch = chain0 + c;
        phiR[c] = phi   + (size_t)ch * L_CONST;
        psiS[c] = psi   + (size_t)ch * L_CONST + base;
        omgS[c] = omega + (size_t)ch * L_CONST + base;
        blS[c]  = bl + (size_t)ch * L_CONST * 3 + 3 * base;
        baS[c]  = ba + (size_t)ch * L_CONST * 3 + 3 * base;
    }

    // ---- phi for 4 steps, both chains: phi[base+1 .. base+4] ----
    float phv[NC][4];
#pragma unroll
    for (int c = 0; c < NC; c++) {
        float4 phq = *(const float4*)(phiR[c] + base);
        float ph3 = __shfl_down_sync(0xffffffffu, phq.x, 1);
        if (lane == 31) {
            int ip = base + SEG;
            ph3 = (ip < L_CONST) ? phiR[c][ip] : 0.f;
        }
        phv[c][0] = phq.y; phv[c][1] = phq.z; phv[c][2] = phq.w; phv[c][3] = ph3;
    }

    // ---- Pass 1: two independent frame chains, interleaved (ILP2) ----
    Frame Fr[NC];
#pragma unroll
    for (int c = 0; c < NC; c++) Fr[c] = frameOfTriplet(A0, B0, C0);

#pragma unroll
    for (int g = 0; g < 2; g++) {
        float psf[NC][2], omf[NC][2], blf[NC][6], baf[NC][6];
#pragma unroll
        for (int c = 0; c < NC; c++) {
            float2 ps  = *(const float2*)(psiS[c] + 2 * g);
            float2 om  = *(const float2*)(omgS[c] + 2 * g);
            float2 b0  = *(const float2*)(blS[c] + 6 * g + 0);
            float2 b1  = *(const float2*)(blS[c] + 6 * g + 2);
            float2 b2  = *(const float2*)(blS[c] + 6 * g + 4);
            float2 a0  = *(const float2*)(baS[c] + 6 * g + 0);
            float2 a1  = *(const float2*)(baS[c] + 6 * g + 2);
            float2 a2  = *(const float2*)(baS[c] + 6 * g + 4);
            psf[c][0] = ps.x; psf[c][1] = ps.y;
            omf[c][0] = om.x; omf[c][1] = om.y;
            blf[c][0] = b0.x; blf[c][1] = b0.y; blf[c][2] = b1.x;
            blf[c][3] = b1.y; blf[c][4] = b2.x; blf[c][5] = b2.y;
            baf[c][0] = a0.x; baf[c][1] = a0.y; baf[c][2] = a1.x;
            baf[c][3] = a1.y; baf[c][4] = a2.x; baf[c][5] = a2.y;
        }
#pragma unroll
        for (int t2 = 0; t2 < 2; t2++) {
            int t = 2 * g + t2;
            bool ok = (base + t) < NSTEP;
#pragma unroll
            for (int c = 0; c < NC; c++) {
                if (ok) {
                    V3 p1 = placeF(Fr[c], baf[c][3 * t2 + 1], blf[c][3 * t2 + 2], psf[c][t2]);
                    V3 p2 = placeF(Fr[c], baf[c][3 * t2 + 2], blf[c][3 * t2 + 0], omf[c][t2]);
                    V3 p3 = placeF(Fr[c], baf[c][3 * t2 + 0], blf[c][3 * t2 + 1], phv[c][t]);
                    traj[c][9 * t + 0][tid] = p1.x; traj[c][9 * t + 1][tid] = p1.y; traj[c][9 * t + 2][tid] = p1.z;
                    traj[c][9 * t + 3][tid] = p2.x; traj[c][9 * t + 4][tid] = p2.y; traj[c][9 * t + 5][tid] = p2.z;
                    traj[c][9 * t + 6][tid] = p3.x; traj[c][9 * t + 7][tid] = p3.y; traj[c][9 * t + 8][tid] = p3.z;
                }
            }
        }
    }

    // GS the endpoints (R6/R8 lesson: scan inputs must be exact rotations).
#pragma unroll
    for (int c = 0; c < NC; c++) orthonormalize(Fr[c]);

    // ---- Conjugated segment transforms + interleaved Kogge-Stone scan ----
    const Aff F0i = invRigid(frameToAff(frameOfTriplet(A0, B0, C0)));
    Aff P[NC];
#pragma unroll
    for (int c = 0; c < NC; c++) P[c] = compose(frameToAff(Fr[c]), F0i);

#pragma unroll
    for (int off = 1; off < 32; off <<= 1) {
#pragma unroll
        for (int c = 0; c < NC; c++) {
            Aff prev = shflUpAff(P[c], off);
            Aff comb = compose(prev, P[c]);
            if (lane >= off) P[c] = comb;
        }
    }

    if (lane == 31 && warp < 3) {
#pragma unroll
        for (int c = 0; c < NC; c++) {
#pragma unroll
            for (int k = 0; k < 9; k++) warpTot[c][warp][k] = P[c].m[k];
#pragma unroll
            for (int k = 0; k < 3; k++) warpTot[c][warp][9 + k] = P[c].t[k];
        }
    }

    Aff Pex[NC];
#pragma unroll
    for (int c = 0; c < NC; c++) Pex[c] = shflUpAff(P[c], 1);
    __syncthreads();

    Aff W[NC];
#pragma unroll
    for (int c = 0; c < NC; c++) {
        W[c] = (lane == 0) ? identityAff() : Pex[c];
        for (int v = warp - 1; v >= 0; v--) {
            Aff T;
#pragma unroll
            for (int k = 0; k < 9; k++) T.m[k] = warpTot[c][v][k];
#pragma unroll
            for (int k = 0; k < 3; k++) T.t[k] = warpTot[c][v][9 + k];
            W[c] = compose(T, W[c]);
        }
    }

    // ---- Pass 2: transform local trajectories in SMEM (interleaved) ----
#pragma unroll
    for (int s = 0; s < SEG; s++) {
#pragma unroll
        for (int p = 0; p < 3; p++) {
#pragma unroll
            for (int c = 0; c < NC; c++) {
                V3 v;
                v.x = traj[c][9 * s + 3 * p + 0][tid];
                v.y = traj[c][9 * s + 3 * p + 1][tid];
                v.z = traj[c][9 * s + 3 * p + 2][tid];
                float wx = W[c].m[0] * v.x + W[c].m[1] * v.y + W[c].m[2] * v.z + W[c].t[0];
                float wy = W[c].m[3] * v.x + W[c].m[4] * v.y + W[c].m[5] * v.z + W[c].t[1];
                float wz = W[c].m[6] * v.x + W[c].m[7] * v.y + W[c].m[8] * v.z + W[c].t[2];
                traj[c][9 * s + 3 * p + 0][tid] = wx;
                traj[c][9 * s + 3 * p + 1][tid] = wy;
                traj[c][9 * s + 3 * p + 2][tid] = wz;
            }
        }
    }
    __syncthreads();

    // ---- Writeout: coalesced incremental walk, shared state, 2 chains ----
    float* outC[NC];
    const float* trajF[NC];
#pragma unroll
    for (int c = 0; c < NC; c++) {
        outC[c] = out + (size_t)(chain0 + c) * CHAIN_FLOATS;
        trajF[c] = &traj[c][0][0];
    }

    // Iteration 0 (tid<9 -> init constants).
    {
        int g0 = tid - 9;
        int ow0 = g0 / 36;
        int rw0 = g0 - 36 * ow0;
        int off0 = rw0 * COLS + ow0;
#pragma unroll
        for (int c = 0; c < NC; c++) {
            float v = (tid < 9) ? c9[tid] : trajF[c][off0];
            outC[c][tid] = v;
        }
    }
    // Walk state for iteration 1: g1 = tid + 119.
    int g1 = tid + 119;
    int ow = g1 / 36;
    int rw = g1 - 36 * ow;
    int off = rw * COLS + ow;
#pragma unroll
    for (int it = 1; it < CHAIN_FLOATS / THREADS; it++) {
#pragma unroll
        for (int c = 0; c < NC; c++) {
            outC[c][it * THREADS + tid] = trajF[c][off];
        }
        rw += 20;
        off += 20 * COLS + 3;
        if (rw >= ROWS) { rw -= ROWS; off -= (ROWS * COLS - 1); }
    }
}

} // anonymous namespace

extern "C" void kernel_launch(void* const* d_in, const int* in_sizes, int n_in,
                              void* d_out, int out_size) {
    const float* phi   = (const float*)d_in[0];
    const float* psi   = (const float*)d_in[1];
    const float* omega = (const float*)d_in[2];
    const float* bl    = (const float*)d_in[3];
    const float* ba    = (const float*)d_in[4];

    const int B = in_sizes[0] / L_CONST;

    nerf_kernel<<<B / NC, THREADS>>>(phi, psi, omega, bl, ba, (float*)d_out);
}

// round 12
// speedup vs baseline: 1.2212x; 1.2212x over previous
#include <cuda_runtime.h>
#include <math.h>

// DifferentiableNERF, round 12.
// R9 baseline (SEG=4, 128 threads/chain, transposed conflict-free SMEM,
// closed-form frame propagation + end-of-segment Gram-Schmidt, matrix
// Kogge-Stone scan, division-free incremental writeout), plus:
//  1. Canonical frame F0 (axes) and F0^-1 translation computed ON THE HOST in
//     double precision, passed by value (constant bank) — removes ~90 instr
//     of per-thread runtime constant recomputation (rsqrtf blocks folding).
//     F0^-1's rotation rows are the same 9 axis numbers (transpose).
//  2. Pass-1 bounds guard removed: only thread 127/t=3 is out of range; its
//     inputs are in-bounds, its traj rows are never read by the writeout
//     (max g=4598 -> row 26 of owner 127), and its P feeds no consumer.

namespace {

constexpr int L_CONST = 512;
constexpr int NSTEP = L_CONST - 1;   // 511
constexpr int SEG = 4;               // steps per thread
constexpr int THREADS = 128;         // 4 warps = 1 chain
constexpr int CHAIN_FLOATS = 3 * L_CONST * 3;  // 4608
constexpr int ROWS = SEG * 9;        // 36
constexpr int COLS = THREADS + 1;    // 129 (conflict-free stride)

struct FC { float ex[3]; float ey[3]; float ez[3]; float t[3]; };  // F0 axes + F0i translation

struct V3 { float x, y, z; };

__device__ __forceinline__ V3 vcross(V3 a, V3 b) {
    return { a.y * b.z - a.z * b.y,
             a.z * b.x - a.x * b.z,
             a.x * b.y - a.y * b.x };
}
__device__ __forceinline__ float vdot(V3 a, V3 b) { return a.x * b.x + a.y * b.y + a.z * b.z; }
__device__ __forceinline__ V3 vunit(V3 a) {
    float r = rsqrtf(fmaxf(vdot(a, a), 1e-30f));
    return { a.x * r, a.y * r, a.z * r };
}

struct Aff { float m[9]; float t[3]; };

__device__ __forceinline__ Aff identityAff() {
    Aff r;
    r.m[0] = 1.f; r.m[1] = 0.f; r.m[2] = 0.f;
    r.m[3] = 0.f; r.m[4] = 1.f; r.m[5] = 0.f;
    r.m[6] = 0.f; r.m[7] = 0.f; r.m[8] = 1.f;
    r.t[0] = 0.f; r.t[1] = 0.f; r.t[2] = 0.f;
    return r;
}

// (A o B)(x) = A(B(x))
__device__ __forceinline__ Aff compose(const Aff& A, const Aff& B) {
    Aff r;
#pragma unroll
    for (int i = 0; i < 3; i++) {
#pragma unroll
        for (int j = 0; j < 3; j++) {
            r.m[3 * i + j] = A.m[3 * i + 0] * B.m[0 + j]
                           + A.m[3 * i + 1] * B.m[3 + j]
                           + A.m[3 * i + 2] * B.m[6 + j];
        }
        r.t[i] = A.m[3 * i + 0] * B.t[0]
               + A.m[3 * i + 1] * B.t[1]
               + A.m[3 * i + 2] * B.t[2] + A.t[i];
    }
    return r;
}

// Orthonormal placement frame: ex = bond dir, ez = plane normal, ey = ez x ex.
struct Frame { V3 ex, ey, ez; V3 c; };

__device__ __forceinline__ V3 placeF(Frame& F, float ang, float len, float tor) {
    float st, ct, sa, ca;
    __sincosf(tor, &st, &ct);
    __sincosf(ang, &sa, &ca);
    float k2 = ct * sa, k3 = st * sa;
    V3 u  = { k3 * F.ez.x + (k2 * F.ey.x - ca * F.ex.x),
              k3 * F.ez.y + (k2 * F.ey.y - ca * F.ex.y),
              k3 * F.ez.z + (k2 * F.ey.z - ca * F.ex.z) };
    V3 p  = { F.c.x + len * u.x, F.c.y + len * u.y, F.c.z + len * u.z };
    V3 ez2 = { ct * F.ez.x - st * F.ey.x,
               ct * F.ez.y - st * F.ey.y,
               ct * F.ez.z - st * F.ey.z };
    V3 ey2 = vcross(ez2, u);
    F.ex = u; F.ey = ey2; F.ez = ez2; F.c = p;
    return p;
}

// Gram-Schmidt: restore exact orthonormality of the propagated frame.
__device__ __forceinline__ void orthonormalize(Frame& F) {
    V3 ex = vunit(F.ex);
    float d = vdot(F.ez, ex);
    V3 ez = { F.ez.x - d * ex.x, F.ez.y - d * ex.y, F.ez.z - d * ex.z };
    ez = vunit(ez);
    F.ex = ex;
    F.ez = ez;
    F.ey = vcross(ez, ex);
}

__device__ __forceinline__ Aff frameToAff(const Frame& F) {
    Aff A;
    A.m[0] = F.ex.x; A.m[1] = F.ey.x; A.m[2] = F.ez.x;
    A.m[3] = F.ex.y; A.m[4] = F.ey.y; A.m[5] = F.ez.y;
    A.m[6] = F.ex.z; A.m[7] = F.ey.z; A.m[8] = F.ez.z;
    A.t[0] = F.c.x;  A.t[1] = F.c.y;  A.t[2] = F.c.z;
    return A;
}

__device__ __forceinline__ Aff shflUpAff(const Aff& A, int delta) {
    Aff r;
#pragma unroll
    for (int k = 0; k < 9; k++) r.m[k] = __shfl_up_sync(0xffffffffu, A.m[k], delta);
#pragma unroll
    for (int k = 0; k < 3; k++) r.t[k] = __shfl_up_sync(0xffffffffu, A.t[k], delta);
    return r;
}

__constant__ float c9[9] = {
    17.047f, 14.099f, 3.625f,
    16.967f, 12.784f, 4.338f,
    15.685f, 12.755f, 5.133f
};

__global__ __launch_bounds__(THREADS, 7)
void nerf_kernel(const float* __restrict__ phi,
                 const float* __restrict__ psi,
                 const float* __restrict__ omega,
                 const float* __restrict__ bl,
                 const float* __restrict__ ba,
                 float* __restrict__ out,
                 const FC fc) {
    __shared__ float traj[ROWS][COLS];
    __shared__ float warpTot[3][12];   // inclusive totals of warps 0..2

    const int tid  = threadIdx.x;
    const int lane = tid & 31;
    const int warp = tid >> 5;
    const int chain = blockIdx.x;

    const int base = tid * SEG;

    const float* __restrict__ phiR = phi   + (size_t)chain * L_CONST;
    const float* __restrict__ psiS = psi   + (size_t)chain * L_CONST + base;
    const float* __restrict__ omgS = omega + (size_t)chain * L_CONST + base;
    const float* __restrict__ blS  = bl + (size_t)chain * L_CONST * 3 + 3 * base;
    const float* __restrict__ baS  = ba + (size_t)chain * L_CONST * 3 + 3 * base;

    // ---- Batched vector loads of this thread's 4-step inputs ----
    float4 psq = *(const float4*)psiS;
    float4 omq = *(const float4*)omgS;
    float4 blq[3], baq[3];
#pragma unroll
    for (int q = 0; q < 3; q++) {
        blq[q] = *(const float4*)(blS + 4 * q);
        baq[q] = *(const float4*)(baS + 4 * q);
    }
    float4 phq = *(const float4*)(phiR + base);   // phi[base .. base+3]
    float ph3 = __shfl_down_sync(0xffffffffu, phq.x, 1);   // phi[base+4]
    if (lane == 31) {
        int ip = base + SEG;
        if (ip > NSTEP) ip = NSTEP;   // in-bounds; value only reaches a dead row
        ph3 = phiR[ip];
    }
    float phv[4] = { phq.y, phq.z, phq.w, ph3 };
    const float* psf = (const float*)&psq;
    const float* omf = (const float*)&omq;
    const float* blf = (const float*)blq;
    const float* baf = (const float*)baq;

    // ---- Pass 1: closed-form frame propagation from canonical init ----
    // Initial frame from host-computed (double-precision) constants.
    Frame Fr;
    Fr.ex = { fc.ex[0], fc.ex[1], fc.ex[2] };
    Fr.ey = { fc.ey[0], fc.ey[1], fc.ey[2] };
    Fr.ez = { fc.ez[0], fc.ez[1], fc.ez[2] };
    Fr.c  = { 15.685f, 12.755f, 5.133f };

#pragma unroll
    for (int t = 0; t < SEG; t++) {
        // Unguarded: only thread 127/t=3 is past NSTEP; its inputs are
        // in-bounds, its traj rows (27..35 of owner 127) are never read,
        // and its P reaches no consumer in the scan.
        V3 p1 = placeF(Fr, baf[3 * t + 1], blf[3 * t + 2], psf[t]);
        V3 p2 = placeF(Fr, baf[3 * t + 2], blf[3 * t + 0], omf[t]);
        V3 p3 = placeF(Fr, baf[3 * t + 0], blf[3 * t + 1], phv[t]);
        traj[9 * t + 0][tid] = p1.x; traj[9 * t + 1][tid] = p1.y; traj[9 * t + 2][tid] = p1.z;
        traj[9 * t + 3][tid] = p2.x; traj[9 * t + 4][tid] = p2.y; traj[9 * t + 5][tid] = p2.z;
        traj[9 * t + 6][tid] = p3.x; traj[9 * t + 7][tid] = p3.y; traj[9 * t + 8][tid] = p3.z;
    }

    // Scan inputs must be exact rotations (R6/R8 lesson): GS the endpoint.
    orthonormalize(Fr);

    // ---- Conjugated segment transform: H' = F(end) o F0^-1 ----
    // F0^-1 rotation rows are the F0 axes; translation from host constants.
    Aff F0i;
    F0i.m[0] = fc.ex[0]; F0i.m[1] = fc.ex[1]; F0i.m[2] = fc.ex[2];
    F0i.m[3] = fc.ey[0]; F0i.m[4] = fc.ey[1]; F0i.m[5] = fc.ey[2];
    F0i.m[6] = fc.ez[0]; F0i.m[7] = fc.ez[1]; F0i.m[8] = fc.ez[2];
    F0i.t[0] = fc.t[0];  F0i.t[1] = fc.t[1];  F0i.t[2] = fc.t[2];

    Aff P = compose(frameToAff(Fr), F0i);

    // Warp inclusive Kogge-Stone scan
#pragma unroll
    for (int off = 1; off < 32; off <<= 1) {
        Aff prev = shflUpAff(P, off);
        Aff comb = compose(prev, P);
        if (lane >= off) P = comb;
    }

    // Publish warp totals
    if (lane == 31 && warp < 3) {
#pragma unroll
        for (int k = 0; k < 9; k++) warpTot[warp][k] = P.m[k];
#pragma unroll
        for (int k = 0; k < 3; k++) warpTot[warp][9 + k] = P.t[k];
    }

    Aff Pex = shflUpAff(P, 1);   // warp-local exclusive prefix
    __syncthreads();

    // W = warpTot[0] o ... o warpTot[warp-1] o Pex   (exclusive prefix = W)
    Aff W = (lane == 0) ? identityAff() : Pex;
    for (int v = warp - 1; v >= 0; v--) {
        Aff T;
#pragma unroll
        for (int k = 0; k < 9; k++) T.m[k] = warpTot[v][k];
#pragma unroll
        for (int k = 0; k < 3; k++) T.t[k] = warpTot[v][9 + k];
        W = compose(T, W);
    }

    // ---- Pass 2: transform local trajectory in SMEM ----
#pragma unroll
    for (int s = 0; s < SEG; s++) {
#pragma unroll
        for (int p = 0; p < 3; p++) {
            V3 v;
            v.x = traj[9 * s + 3 * p + 0][tid];
            v.y = traj[9 * s + 3 * p + 1][tid];
            v.z = traj[9 * s + 3 * p + 2][tid];
            float wx = W.m[0] * v.x + W.m[1] * v.y + W.m[2] * v.z + W.t[0];
            float wy = W.m[3] * v.x + W.m[4] * v.y + W.m[5] * v.z + W.t[1];
            float wz = W.m[6] * v.x + W.m[7] * v.y + W.m[8] * v.z + W.t[2];
            traj[9 * s + 3 * p + 0][tid] = wx;
            traj[9 * s + 3 * p + 1][tid] = wy;
            traj[9 * s + 3 * p + 2][tid] = wz;
        }
    }
    __syncthreads();

    // ---- Writeout: coalesced, division-free incremental walk ----
    float* __restrict__ outC = out + (size_t)chain * CHAIN_FLOATS;
    const float* trajF = &traj[0][0];

    // Iteration 0 (tid<9 -> init constants).
    {
        float v;
        if (tid < 9) {
            v = c9[tid];
        } else {
            int g0 = tid - 9;
            int ow0 = g0 / 36;
            int rw0 = g0 - 36 * ow0;
            v = trajF[rw0 * COLS + ow0];
        }
        outC[tid] = v;
    }
    // Walk state for iteration 1: g1 = tid + 119.
    int g1 = tid + 119;
    int ow = g1 / 36;
    int rw = g1 - 36 * ow;
    const float* p = trajF + rw * COLS + ow;
#pragma unroll
    for (int it = 1; it < CHAIN_FLOATS / THREADS; it++) {
        outC[it * THREADS + tid] = *p;
        rw += 20;
        p += 20 * COLS + 3;
        if (rw >= ROWS) { rw -= ROWS; p -= (ROWS * COLS - 1); }
    }
}

} // anonymous namespace

extern "C" void kernel_launch(void* const* d_in, const int* in_sizes, int n_in,
                              void* d_out, int out_size) {
    const float* phi   = (const float*)d_in[0];
    const float* psi   = (const float*)d_in[1];
    const float* omega = (const float*)d_in[2];
    const float* bl    = (const float*)d_in[3];
    const float* ba    = (const float*)d_in[4];

    const int B = in_sizes[0] / L_CONST;

    // Canonical frame of (A0, B0, C0) in double precision:
    // ex = unit(C0-B0); ez = unit(cross(B0-A0, ex)); ey = ez x ex;
    // F0^-1 translation = -(ex.C0, ey.C0, ez.C0).
    const double A0[3] = {17.047, 14.099, 3.625};
    const double B0[3] = {16.967, 12.784, 4.338};
    const double C0[3] = {15.685, 12.755, 5.133};
    double ex[3], ab[3], ez[3], ey[3];
    for (int i = 0; i < 3; i++) { ex[i] = C0[i] - B0[i]; ab[i] = B0[i] - A0[i]; }
    double n = sqrt(ex[0]*ex[0] + ex[1]*ex[1] + ex[2]*ex[2]);
    for (int i = 0; i < 3; i++) ex[i] /= n;
    ez[0] = ab[1]*ex[2] - ab[2]*ex[1];
    ez[1] = ab[2]*ex[0] - ab[0]*ex[2];
    ez[2] = ab[0]*ex[1] - ab[1]*ex[0];
    n = sqrt(ez[0]*ez[0] + ez[1]*ez[1] + ez[2]*ez[2]);
    for (int i = 0; i < 3; i++) ez[i] /= n;
    ey[0] = ez[1]*ex[2] - ez[2]*ex[1];
    ey[1] = ez[2]*ex[0] - ez[0]*ex[2];
    ey[2] = ez[0]*ex[1] - ez[1]*ex[0];

    FC fc;
    for (int i = 0; i < 3; i++) {
        fc.ex[i] = (float)ex[i];
        fc.ey[i] = (float)ey[i];
        fc.ez[i] = (float)ez[i];
    }
    fc.t[0] = (float)(-(ex[0]*C0[0] + ex[1]*C0[1] + ex[2]*C0[2]));
    fc.t[1] = (float)(-(ey[0]*C0[0] + ey[1]*C0[1] + ey[2]*C0[2]));
    fc.t[2] = (float)(-(ez[0]*C0[0] + ez[1]*C0[1] + ez[2]*C0[2]));

    nerf_kernel<<<B, THREADS>>>(phi, psi, omega, bl, ba, (float*)d_out, fc);
}

// round 13
// speedup vs baseline: 1.2964x; 1.0616x over previous
#include <cuda_runtime.h>
#include <math.h>

// DifferentiableNERF, round 13.
// R12 baseline (SEG=4, 128 threads/chain, transposed conflict-free SMEM,
// closed-form frame propagation + end-of-segment Gram-Schmidt, matrix
// Kogge-Stone scan, host-computed F0 constants, unguarded pass 1), plus:
// float4-group writeout: 9x STG.128 per thread instead of 36x STG.32, with a
// division-free (ow += 14, rw += 8 mod 36) group walk and per-element
// predicated wrap for the <=1 owner boundary inside each float4.

namespace {

constexpr int L_CONST = 512;
constexpr int NSTEP = L_CONST - 1;   // 511
constexpr int SEG = 4;               // steps per thread
constexpr int THREADS = 128;         // 4 warps = 1 chain
constexpr int CHAIN_FLOATS = 3 * L_CONST * 3;  // 4608
constexpr int ROWS = SEG * 9;        // 36
constexpr int COLS = THREADS + 1;    // 129 (conflict-free stride)
constexpr int WRAP = ROWS * COLS - 1;          // 4643
constexpr int STEP_PTR = 8 * COLS + 14;        // 1046 (g += 512)

struct FC { float ex[3]; float ey[3]; float ez[3]; float t[3]; };

struct V3 { float x, y, z; };

__device__ __forceinline__ V3 vcross(V3 a, V3 b) {
    return { a.y * b.z - a.z * b.y,
             a.z * b.x - a.x * b.z,
             a.x * b.y - a.y * b.x };
}
__device__ __forceinline__ float vdot(V3 a, V3 b) { return a.x * b.x + a.y * b.y + a.z * b.z; }
__device__ __forceinline__ V3 vunit(V3 a) {
    float r = rsqrtf(fmaxf(vdot(a, a), 1e-30f));
    return { a.x * r, a.y * r, a.z * r };
}

struct Aff { float m[9]; float t[3]; };

__device__ __forceinline__ Aff identityAff() {
    Aff r;
    r.m[0] = 1.f; r.m[1] = 0.f; r.m[2] = 0.f;
    r.m[3] = 0.f; r.m[4] = 1.f; r.m[5] = 0.f;
    r.m[6] = 0.f; r.m[7] = 0.f; r.m[8] = 1.f;
    r.t[0] = 0.f; r.t[1] = 0.f; r.t[2] = 0.f;
    return r;
}

// (A o B)(x) = A(B(x))
__device__ __forceinline__ Aff compose(const Aff& A, const Aff& B) {
    Aff r;
#pragma unroll
    for (int i = 0; i < 3; i++) {
#pragma unroll
        for (int j = 0; j < 3; j++) {
            r.m[3 * i + j] = A.m[3 * i + 0] * B.m[0 + j]
                           + A.m[3 * i + 1] * B.m[3 + j]
                           + A.m[3 * i + 2] * B.m[6 + j];
        }
        r.t[i] = A.m[3 * i + 0] * B.t[0]
               + A.m[3 * i + 1] * B.t[1]
               + A.m[3 * i + 2] * B.t[2] + A.t[i];
    }
    return r;
}

// Orthonormal placement frame: ex = bond dir, ez = plane normal, ey = ez x ex.
struct Frame { V3 ex, ey, ez; V3 c; };

__device__ __forceinline__ V3 placeF(Frame& F, float ang, float len, float tor) {
    float st, ct, sa, ca;
    __sincosf(tor, &st, &ct);
    __sincosf(ang, &sa, &ca);
    float k2 = ct * sa, k3 = st * sa;
    V3 u  = { k3 * F.ez.x + (k2 * F.ey.x - ca * F.ex.x),
              k3 * F.ez.y + (k2 * F.ey.y - ca * F.ex.y),
              k3 * F.ez.z + (k2 * F.ey.z - ca * F.ex.z) };
    V3 p  = { F.c.x + len * u.x, F.c.y + len * u.y, F.c.z + len * u.z };
    V3 ez2 = { ct * F.ez.x - st * F.ey.x,
               ct * F.ez.y - st * F.ey.y,
               ct * F.ez.z - st * F.ey.z };
    V3 ey2 = vcross(ez2, u);
    F.ex = u; F.ey = ey2; F.ez = ez2; F.c = p;
    return p;
}

// Gram-Schmidt: restore exact orthonormality of the propagated frame.
__device__ __forceinline__ void orthonormalize(Frame& F) {
    V3 ex = vunit(F.ex);
    float d = vdot(F.ez, ex);
    V3 ez = { F.ez.x - d * ex.x, F.ez.y - d * ex.y, F.ez.z - d * ex.z };
    ez = vunit(ez);
    F.ex = ex;
    F.ez = ez;
    F.ey = vcross(ez, ex);
}

__device__ __forceinline__ Aff frameToAff(const Frame& F) {
    Aff A;
    A.m[0] = F.ex.x; A.m[1] = F.ey.x; A.m[2] = F.ez.x;
    A.m[3] = F.ex.y; A.m[4] = F.ey.y; A.m[5] = F.ez.y;
    A.m[6] = F.ex.z; A.m[7] = F.ey.z; A.m[8] = F.ez.z;
    A.t[0] = F.c.x;  A.t[1] = F.c.y;  A.t[2] = F.c.z;
    return A;
}

__device__ __forceinline__ Aff shflUpAff(const Aff& A, int delta) {
    Aff r;
#pragma unroll
    for (int k = 0; k < 9; k++) r.m[k] = __shfl_up_sync(0xffffffffu, A.m[k], delta);
#pragma unroll
    for (int k = 0; k < 3; k++) r.t[k] = __shfl_up_sync(0xffffffffu, A.t[k], delta);
    return r;
}

__constant__ float c9[12] = {
    17.047f, 14.099f, 3.625f,
    16.967f, 12.784f, 4.338f,
    15.685f, 12.755f, 5.133f,
    0.f, 0.f, 0.f
};

__global__ __launch_bounds__(THREADS, 7)
void nerf_kernel(const float* __restrict__ phi,
                 const float* __restrict__ psi,
                 const float* __restrict__ omega,
                 const float* __restrict__ bl,
                 const float* __restrict__ ba,
                 float* __restrict__ out,
                 const FC fc) {
    __shared__ float traj[ROWS][COLS];
    __shared__ float warpTot[3][12];   // inclusive totals of warps 0..2

    const int tid  = threadIdx.x;
    const int lane = tid & 31;
    const int warp = tid >> 5;
    const int chain = blockIdx.x;

    const int base = tid * SEG;

    const float* __restrict__ phiR = phi   + (size_t)chain * L_CONST;
    const float* __restrict__ psiS = psi   + (size_t)chain * L_CONST + base;
    const float* __restrict__ omgS = omega + (size_t)chain * L_CONST + base;
    const float* __restrict__ blS  = bl + (size_t)chain * L_CONST * 3 + 3 * base;
    const float* __restrict__ baS  = ba + (size_t)chain * L_CONST * 3 + 3 * base;

    // ---- Batched vector loads of this thread's 4-step inputs ----
    float4 psq = *(const float4*)psiS;
    float4 omq = *(const float4*)omgS;
    float4 blq[3], baq[3];
#pragma unroll
    for (int q = 0; q < 3; q++) {
        blq[q] = *(const float4*)(blS + 4 * q);
        baq[q] = *(const float4*)(baS + 4 * q);
    }
    float4 phq = *(const float4*)(phiR + base);   // phi[base .. base+3]
    float ph3 = __shfl_down_sync(0xffffffffu, phq.x, 1);   // phi[base+4]
    if (lane == 31) {
        int ip = base + SEG;
        if (ip > NSTEP) ip = NSTEP;   // in-bounds; value only reaches a dead row
        ph3 = phiR[ip];
    }
    float phv[4] = { phq.y, phq.z, phq.w, ph3 };
    const float* psf = (const float*)&psq;
    const float* omf = (const float*)&omq;
    const float* blf = (const float*)blq;
    const float* baf = (const float*)baq;

    // ---- Pass 1: closed-form frame propagation from canonical init ----
    Frame Fr;
    Fr.ex = { fc.ex[0], fc.ex[1], fc.ex[2] };
    Fr.ey = { fc.ey[0], fc.ey[1], fc.ey[2] };
    Fr.ez = { fc.ez[0], fc.ez[1], fc.ez[2] };
    Fr.c  = { 15.685f, 12.755f, 5.133f };

#pragma unroll
    for (int t = 0; t < SEG; t++) {
        // Unguarded: only thread 127/t=3 is past NSTEP; its inputs are
        // in-bounds, its traj rows (27..35 of owner 127) are never read,
        // and its P feeds no consumer in the scan.
        V3 p1 = placeF(Fr, baf[3 * t + 1], blf[3 * t + 2], psf[t]);
        V3 p2 = placeF(Fr, baf[3 * t + 2], blf[3 * t + 0], omf[t]);
        V3 p3 = placeF(Fr, baf[3 * t + 0], blf[3 * t + 1], phv[t]);
        traj[9 * t + 0][tid] = p1.x; traj[9 * t + 1][tid] = p1.y; traj[9 * t + 2][tid] = p1.z;
        traj[9 * t + 3][tid] = p2.x; traj[9 * t + 4][tid] = p2.y; traj[9 * t + 5][tid] = p2.z;
        traj[9 * t + 6][tid] = p3.x; traj[9 * t + 7][tid] = p3.y; traj[9 * t + 8][tid] = p3.z;
    }

    // Scan inputs must be exact rotations (R6/R8 lesson): GS the endpoint.
    orthonormalize(Fr);

    // ---- Conjugated segment transform: H' = F(end) o F0^-1 ----
    Aff F0i;
    F0i.m[0] = fc.ex[0]; F0i.m[1] = fc.ex[1]; F0i.m[2] = fc.ex[2];
    F0i.m[3] = fc.ey[0]; F0i.m[4] = fc.ey[1]; F0i.m[5] = fc.ey[2];
    F0i.m[6] = fc.ez[0]; F0i.m[7] = fc.ez[1]; F0i.m[8] = fc.ez[2];
    F0i.t[0] = fc.t[0];  F0i.t[1] = fc.t[1];  F0i.t[2] = fc.t[2];

    Aff P = compose(frameToAff(Fr), F0i);

    // Warp inclusive Kogge-Stone scan
#pragma unroll
    for (int off = 1; off < 32; off <<= 1) {
        Aff prev = shflUpAff(P, off);
        Aff comb = compose(prev, P);
        if (lane >= off) P = comb;
    }

    // Publish warp totals
    if (lane == 31 && warp < 3) {
#pragma unroll
        for (int k = 0; k < 9; k++) warpTot[warp][k] = P.m[k];
#pragma unroll
        for (int k = 0; k < 3; k++) warpTot[warp][9 + k] = P.t[k];
    }

    Aff Pex = shflUpAff(P, 1);   // warp-local exclusive prefix
    __syncthreads();

    // W = warpTot[0] o ... o warpTot[warp-1] o Pex   (exclusive prefix = W)
    Aff W = (lane == 0) ? identityAff() : Pex;
    for (int v = warp - 1; v >= 0; v--) {
        Aff T;
#pragma unroll
        for (int k = 0; k < 9; k++) T.m[k] = warpTot[v][k];
#pragma unroll
        for (int k = 0; k < 3; k++) T.t[k] = warpTot[v][9 + k];
        W = compose(T, W);
    }

    // ---- Pass 2: transform local trajectory in SMEM ----
#pragma unroll
    for (int s = 0; s < SEG; s++) {
#pragma unroll
        for (int p = 0; p < 3; p++) {
            V3 v;
            v.x = traj[9 * s + 3 * p + 0][tid];
            v.y = traj[9 * s + 3 * p + 1][tid];
            v.z = traj[9 * s + 3 * p + 2][tid];
            float wx = W.m[0] * v.x + W.m[1] * v.y + W.m[2] * v.z + W.t[0];
            float wy = W.m[3] * v.x + W.m[4] * v.y + W.m[5] * v.z + W.t[1];
            float wz = W.m[6] * v.x + W.m[7] * v.y + W.m[8] * v.z + W.t[2];
            traj[9 * s + 3 * p + 0][tid] = wx;
            traj[9 * s + 3 * p + 1][tid] = wy;
            traj[9 * s + 3 * p + 2][tid] = wz;
        }
    }
    __syncthreads();

    // ---- Writeout: float4 groups, division-free group walk ----
    // float4 index q = it*128 + tid (it = 0..8); floats f = 4q..4q+3,
    // element g = f - 9 lives at traj[g % 36][g / 36].
    // Group advance: g += 512 => ow += 14, rw += 8 (mod 36, one wrap max).
    float* __restrict__ outC = out + (size_t)chain * CHAIN_FLOATS;
    float4* __restrict__ outV = (float4*)outC;
    const float* trajF = &traj[0][0];

    // Iteration 0.
    if (tid < 3) {
        // f = 0..11: init constants (f<9) then owner 0 rows 0..2.
#pragma unroll
        for (int w = 0; w < 4; w++) {
            int f = 4 * tid + w;
            outC[f] = (f < 9) ? c9[f] : trajF[(f - 9) * COLS];
        }
    } else {
        int g0 = 4 * tid - 9;
        int ow0 = g0 / 36;
        int rw0 = g0 - 36 * ow0;
        const float* p0 = trajF + rw0 * COLS + ow0;
        float vv[4];
#pragma unroll
        for (int w = 0; w < 4; w++) {
            const float* a = p0 + w * COLS;
            if (rw0 + w >= ROWS) a -= WRAP;
            vv[w] = *a;
        }
        outV[tid] = make_float4(vv[0], vv[1], vv[2], vv[3]);
    }

    // Iterations 1..8: state computed directly for g1 = 503 + 4*tid.
    int g1 = 503 + 4 * tid;
    int ow = g1 / 36;
    int rw = g1 - 36 * ow;
    const float* p = trajF + rw * COLS + ow;
#pragma unroll
    for (int it = 1; it < 9; it++) {
        float vv[4];
#pragma unroll
        for (int w = 0; w < 4; w++) {
            const float* a = p + w * COLS;
            if (rw + w >= ROWS) a -= WRAP;
            vv[w] = *a;
        }
        outV[it * THREADS + tid] = make_float4(vv[0], vv[1], vv[2], vv[3]);
        rw += 8;
        p += STEP_PTR;
        if (rw >= ROWS) { rw -= ROWS; p -= WRAP; }
    }
}

} // anonymous namespace

extern "C" void kernel_launch(void* const* d_in, const int* in_sizes, int n_in,
                              void* d_out, int out_size) {
    const float* phi   = (const float*)d_in[0];
    const float* psi   = (const float*)d_in[1];
    const float* omega = (const float*)d_in[2];
    const float* bl    = (const float*)d_in[3];
    const float* ba    = (const float*)d_in[4];

    const int B = in_sizes[0] / L_CONST;

    // Canonical frame of (A0, B0, C0) in double precision.
    const double A0[3] = {17.047, 14.099, 3.625};
    const double B0[3] = {16.967, 12.784, 4.338};
    const double C0[3] = {15.685, 12.755, 5.133};
    double ex[3], ab[3], ez[3], ey[3];
    for (int i = 0; i < 3; i++) { ex[i] = C0[i] - B0[i]; ab[i] = B0[i] - A0[i]; }
    double n = sqrt(ex[0]*ex[0] + ex[1]*ex[1] + ex[2]*ex[2]);
    for (int i = 0; i < 3; i++) ex[i] /= n;
    ez[0] = ab[1]*ex[2] - ab[2]*ex[1];
    ez[1] = ab[2]*ex[0] - ab[0]*ex[2];
    ez[2] = ab[0]*ex[1] - ab[1]*ex[0];
    n = sqrt(ez[0]*ez[0] + ez[1]*ez[1] + ez[2]*ez[2]);
    for (int i = 0; i < 3; i++) ez[i] /= n;
    ey[0] = ez[1]*ex[2] - ez[2]*ex[1];
    ey[1] = ez[2]*ex[0] - ez[0]*ex[2];
    ey[2] = ez[0]*ex[1] - ez[1]*ex[0];

    FC fc;
    for (int i = 0; i < 3; i++) {
        fc.ex[i] = (float)ex[i];
        fc.ey[i] = (float)ey[i];
        fc.ez[i] = (float)ez[i];
    }
    fc.t[0] = (float)(-(ex[0]*C0[0] + ex[1]*C0[1] + ex[2]*C0[2]));
    fc.t[1] = (float)(-(ey[0]*C0[0] + ey[1]*C0[1] + ey[2]*C0[2]));
    fc.t[2] = (float)(-(ez[0]*C0[0] + ez[1]*C0[1] + ez[2]*C0[2]));

    nerf_kernel<<<B, THREADS>>>(phi, psi, omega, bl, ba, (float*)d_out, fc);
}